// round 10
// baseline (speedup 1.0000x reference)
#include <cuda_runtime.h>
#include <cuda_fp16.h>
#include <math.h>

#define NN   50000
#define E2n  400000
#define EE   800000
#define PBLK 148
#define PTHR 512
#define PP   2703    // ceil(E2n / PBLK)

typedef unsigned long long ull;
typedef unsigned int uint;

// ---------------- scratch ----------------
__device__ __align__(16) __half g_h16[(size_t)NN * 256];
__device__ __align__(16) float g_lp[(size_t)NN * 8];
__device__ float g_deg[NN];
__device__ float g_logdeg[NN];
__device__ float g_wpre[E2n];
__device__ __align__(32) float g_sumin[11][(size_t)NN * 8];  // pre-zeroed
__device__ __align__(16) float g_R[64];                      // R * log2(e)
__device__ __align__(16) __half g_Wab16[512 * 64];
__device__ __align__(16) __half g_w1h[512 * 256];
__device__ __align__(16) __half g_w1l[512 * 256];
__device__ uint g_barc;     // grid-barrier arrival counter (monotonic per launch)
__device__ uint g_bars;     // grid-barrier released epoch

// ---------------- helpers ----------------
__device__ __forceinline__ void red_add_v4(float* p, float a, float b, float c, float d) {
    ull gp = (ull)__cvta_generic_to_global(p);
    asm volatile("red.global.add.v4.f32 [%0], {%1,%2,%3,%4};"
                 :: "l"(gp), "f"(a), "f"(b), "f"(c), "f"(d) : "memory");
}
__device__ __forceinline__ unsigned smem_u32(const void* p) {
    unsigned a;
    asm("{ .reg .u64 t; cvta.to.shared.u64 t, %1; cvt.u32.u64 %0, t; }" : "=r"(a) : "l"(p));
    return a;
}
__device__ __forceinline__ void cpa16(uint saddr, const void* g) {
    asm volatile("cp.async.cg.shared.global [%0], [%1], 16;" :: "r"(saddr), "l"(g));
}
#define CPA_COMMIT() asm volatile("cp.async.commit_group;")
#define CPA_WAIT1()  asm volatile("cp.async.wait_group 1;")
#define CPA_WAIT0()  asm volatile("cp.async.wait_group 0;")
__device__ __forceinline__ void ldsm4(uint& a, uint& b, uint& c, uint& d, uint addr) {
    asm volatile("ldmatrix.sync.aligned.m8n8.x4.shared.b16 {%0,%1,%2,%3}, [%4];"
                 : "=r"(a), "=r"(b), "=r"(c), "=r"(d) : "r"(addr));
}
__device__ __forceinline__ void ldsm4t(uint& a, uint& b, uint& c, uint& d, uint addr) {
    asm volatile("ldmatrix.sync.aligned.m8n8.x4.trans.shared.b16 {%0,%1,%2,%3}, [%4];"
                 : "=r"(a), "=r"(b), "=r"(c), "=r"(d) : "r"(addr));
}
__device__ __forceinline__ void mma16816(float* acc, const uint* a, uint b0, uint b1) {
    asm volatile("mma.sync.aligned.m16n8k16.row.col.f32.f16.f16.f32 "
                 "{%0,%1,%2,%3}, {%4,%5,%6,%7}, {%8,%9}, {%0,%1,%2,%3};"
                 : "+f"(acc[0]), "+f"(acc[1]), "+f"(acc[2]), "+f"(acc[3])
                 : "r"(a[0]), "r"(a[1]), "r"(a[2]), "r"(a[3]), "r"(b0), "r"(b1));
}
__device__ __forceinline__ uint4 pack8h(const float* v) {
    __half2 a = __floats2half2_rn(v[0], v[1]);
    __half2 b = __floats2half2_rn(v[2], v[3]);
    __half2 c = __floats2half2_rn(v[4], v[5]);
    __half2 d = __floats2half2_rn(v[6], v[7]);
    return make_uint4(*(uint*)&a, *(uint*)&b, *(uint*)&c, *(uint*)&d);
}
__device__ __forceinline__ void unpack8h(uint4 u, float* v) {
    float2 a = __half22float2(*(__half2*)&u.x);
    float2 b = __half22float2(*(__half2*)&u.y);
    float2 c = __half22float2(*(__half2*)&u.z);
    float2 d = __half22float2(*(__half2*)&u.w);
    v[0] = a.x; v[1] = a.y; v[2] = b.x; v[3] = b.y;
    v[4] = c.x; v[5] = c.y; v[6] = d.x; v[7] = d.y;
}
__device__ __forceinline__ float4 ldcg4(const float* p) {
    float4 v;
    asm volatile("ld.global.cg.v4.f32 {%0,%1,%2,%3}, [%4];"
                 : "=f"(v.x), "=f"(v.y), "=f"(v.z), "=f"(v.w) : "l"(p));
    return v;
}

// ---------------- launch 0: prep ----------------
__global__ void k_prep_all(const float* __restrict__ R_raw, const float* __restrict__ rsl,
                           const float* __restrict__ ew1, const float* __restrict__ encw1) {
    int i = blockIdx.x * 256 + threadIdx.x;
    if (i == 0) { g_barc = 0u; g_bars = 0u; }
    if (i < 11 * NN * 8) ((float*)g_sumin)[i] = 0.0f;
    if (i < NN) g_deg[i] = 0.0f;
    if (i < 512 * 64) {
        int k = i >> 6, j = i & 63;
        int c = j >> 3, u = j & 7;
        int pos = (k << 6) + (((c ^ (k & 7)) << 3) + u);
        int hc = k >> 1;
        float v = (k & 1) ? ew1[(256 + hc) * 64 + j] : ew1[hc * 64 + j];
        g_Wab16[pos] = __float2half_rn(v);
    }
    if (i < 512 * 256) {
        float v = encw1[i];
        __half h = __float2half_rn(v);
        g_w1h[i] = h;
        g_w1l[i] = __float2half_rn(v - __half2float(h));
    }
    if (i < 64) {
        int r = i >> 3, c = i & 7;
        float v = 0.5f * (R_raw[r * 8 + c] + R_raw[c * 8 + r]);
        float s = log1pf(expf(rsl[0])) + 1e-6f;
        g_R[i] = s * tanhf(v) * 1.44269504088896f;
    }
}

// ---------------- launch 1: degree ----------------
__global__ void k_deg(const int* __restrict__ ei) {
    int e = blockIdx.x * blockDim.x + threadIdx.x;
    if (e < EE) atomicAdd(&g_deg[ei[e]], 1.0f);
}

// ---------------- launch 2: encoder (unchanged from R9) ----------------
extern __shared__ char enc_pool[];
__global__ void __launch_bounds__(256, 2) k_encoder(const float* __restrict__ x,
                                                    const float* __restrict__ b1,
                                                    const float* __restrict__ w2,
                                                    const float* __restrict__ b2) {
    __shared__ float w2s[256][8];
    __shared__ float b1s[256];
    __shared__ float slog[64][8];
    char* pool = enc_pool;
    uint pbase = smem_u32(pool);
    int tid = threadIdx.x, lane = tid & 31, wid = tid >> 5;
    int mw = wid & 3, nw = wid >> 2;

    if (blockIdx.x < (NN + 255) / 256) {
        int n = blockIdx.x * 256 + tid;
        if (n < NN) g_logdeg[n] = __logf(g_deg[n] + 1.0f);
    }
    for (int i = tid; i < 2048; i += 256) w2s[i >> 3][i & 7] = w2[i];
    if (tid < 256) b1s[tid] = b1[tid];
    for (int i = tid; i < 512; i += 256) ((float*)slog)[i] = 0.0f;

    int n0 = blockIdx.x * 64;

    auto stageA = [&](int kt, int buf) {
        if (tid < 128) {
            int r = tid >> 1, c = tid & 1;
            int gn = min(n0 + r, NN - 1);
            const float4* xr = (const float4*)x + (size_t)gn * 128 + kt * 4 + c * 2;
            float4 f0 = xr[0], f1 = xr[1];
            float v[8] = {f0.x, f0.y, f0.z, f0.w, f1.x, f1.y, f1.z, f1.w};
            __half hi[8], lo[8];
#pragma unroll
            for (int q = 0; q < 8; q++) {
                __half h = __float2half_rn(v[q]);
                hi[q] = h;
                lo[q] = __float2half_rn(v[q] - __half2float(h));
            }
            int cp = c ^ ((r >> 2) & 1);
            *(uint4*)(pool + (buf * 2 + 0) * 2048 + r * 32 + cp * 16) = *(uint4*)hi;
            *(uint4*)(pool + (buf * 2 + 1) * 2048 + r * 32 + cp * 16) = *(uint4*)lo;
        }
    };
    auto stageB = [&](int kt, int buf) {
#pragma unroll
        for (int q = 0; q < 4; q++) {
            int id = tid + 256 * q;
            int which = id >> 9, rem = id & 511, k = rem >> 5, cu = rem & 31;
            const char* src = (const char*)(which ? g_w1l : g_w1h)
                              + (((size_t)(kt * 16 + k) * 32 + cu) << 4);
            int cp = cu ^ (k & 7);
            cpa16(pbase + 8192 + (buf * 2 + which) * 8192 + k * 512 + cp * 16, src);
        }
    };

    stageA(0, 0); stageB(0, 0); CPA_COMMIT();

    float acc[16][4];
#pragma unroll
    for (int t = 0; t < 16; t++)
#pragma unroll
        for (int q = 0; q < 4; q++) acc[t][q] = 0.0f;

    int q4 = lane >> 3, l8 = lane & 7;
    int arow = mw * 16 + (q4 & 1) * 8 + l8;
    uint aoff = (uint)(arow * 32 + (((q4 >> 1) ^ ((arow >> 2) & 1)) * 16));
    int bk = lane & 15, chi = lane >> 4;
    uint bko = (uint)(bk * 512);

    for (int kt = 0; kt < 32; kt++) {
        int buf = kt & 1;
        if (kt < 31) {
            stageA(kt + 1, buf ^ 1); stageB(kt + 1, buf ^ 1); CPA_COMMIT();
            CPA_WAIT1();
        } else {
            CPA_WAIT0();
        }
        __syncthreads();
        uint a1b = pbase + (buf * 2 + 0) * 2048 + aoff;
        uint a2b = pbase + (buf * 2 + 1) * 2048 + aoff;
        uint bhb = pbase + 8192 + (buf * 2 + 0) * 8192 + bko;
        uint blb = pbase + 8192 + (buf * 2 + 1) * 8192 + bko;
        uint A1[4], A2[4];
        ldsm4(A1[0], A1[1], A1[2], A1[3], a1b);
        ldsm4(A2[0], A2[1], A2[2], A2[3], a2b);
#pragma unroll
        for (int t = 0; t < 8; t++) {
            int chunk = nw * 16 + t * 2 + chi;
            uint coff = (uint)((chunk ^ (bk & 7)) * 16);
            uint h0, h1, h2, h3, l0, l1, l2, l3;
            ldsm4t(h0, h1, h2, h3, bhb + coff);
            ldsm4t(l0, l1, l2, l3, blb + coff);
            mma16816(acc[2 * t],     A1, h0, h1);
            mma16816(acc[2 * t + 1], A1, h2, h3);
            mma16816(acc[2 * t],     A1, l0, l1);
            mma16816(acc[2 * t + 1], A1, l2, l3);
            mma16816(acc[2 * t],     A2, h0, h1);
            mma16816(acc[2 * t + 1], A2, h2, h3);
        }
        __syncthreads();
    }

    int r = lane >> 2, c = lane & 3;
    int row0 = mw * 16 + r;
    float pl0[8], pl1[8];
#pragma unroll
    for (int k = 0; k < 8; k++) { pl0[k] = 0.0f; pl1[k] = 0.0f; }
    __half* h16s = (__half*)pool;
#pragma unroll
    for (int tt = 0; tt < 16; tt++) {
        int j0 = nw * 128 + tt * 8 + 2 * c;
        float hv0 = fmaxf(acc[tt][0] + b1s[j0],     0.0f);
        float hv1 = fmaxf(acc[tt][1] + b1s[j0 + 1], 0.0f);
        float hv2 = fmaxf(acc[tt][2] + b1s[j0],     0.0f);
        float hv3 = fmaxf(acc[tt][3] + b1s[j0 + 1], 0.0f);
        *(__half2*)(h16s + row0 * 264 + j0)       = __floats2half2_rn(hv0, hv1);
        *(__half2*)(h16s + (row0 + 8) * 264 + j0) = __floats2half2_rn(hv2, hv3);
        const float4* w2a = (const float4*)w2s[j0];
        const float4* w2b = (const float4*)w2s[j0 + 1];
        float4 a0 = w2a[0], a1 = w2a[1], b0 = w2b[0], b1v = w2b[1];
        pl0[0] += hv0 * a0.x + hv1 * b0.x;  pl0[1] += hv0 * a0.y + hv1 * b0.y;
        pl0[2] += hv0 * a0.z + hv1 * b0.z;  pl0[3] += hv0 * a0.w + hv1 * b0.w;
        pl0[4] += hv0 * a1.x + hv1 * b1v.x; pl0[5] += hv0 * a1.y + hv1 * b1v.y;
        pl0[6] += hv0 * a1.z + hv1 * b1v.z; pl0[7] += hv0 * a1.w + hv1 * b1v.w;
        pl1[0] += hv2 * a0.x + hv3 * b0.x;  pl1[1] += hv2 * a0.y + hv3 * b0.y;
        pl1[2] += hv2 * a0.z + hv3 * b0.z;  pl1[3] += hv2 * a0.w + hv3 * b0.w;
        pl1[4] += hv2 * a1.x + hv3 * b1v.x; pl1[5] += hv2 * a1.y + hv3 * b1v.y;
        pl1[6] += hv2 * a1.z + hv3 * b1v.z; pl1[7] += hv2 * a1.w + hv3 * b1v.w;
    }
#pragma unroll
    for (int k = 0; k < 8; k++) {
        pl0[k] += __shfl_xor_sync(0xffffffffu, pl0[k], 1);
        pl0[k] += __shfl_xor_sync(0xffffffffu, pl0[k], 2);
        pl1[k] += __shfl_xor_sync(0xffffffffu, pl1[k], 1);
        pl1[k] += __shfl_xor_sync(0xffffffffu, pl1[k], 2);
    }
    if (c == 0) {
#pragma unroll
        for (int k = 0; k < 8; k++) {
            atomicAdd(&slog[row0][k], pl0[k]);
            atomicAdd(&slog[row0 + 8][k], pl1[k]);
        }
    }
    __syncthreads();
#pragma unroll
    for (int i = 0; i < 8; i++) {
        int id = tid + 256 * i;
        int row = id >> 5, cu = id & 31;
        int node = n0 + row;
        if (node < NN) {
            uint4 v = ((uint4*)pool)[row * 33 + cu];
            ((uint4*)g_h16)[(size_t)node * 32 + cu] = v;
        }
    }
    if (tid < 64) {
        int node = n0 + tid;
        if (node < NN) {
            float lg[8], mx = -1e30f;
#pragma unroll
            for (int k = 0; k < 8; k++) { lg[k] = slog[tid][k] + b2[k]; mx = fmaxf(mx, lg[k]); }
            float s = 0.0f;
#pragma unroll
            for (int k = 0; k < 8; k++) s += __expf(lg[k] - mx);
            float lse = mx + __logf(s);
#pragma unroll
            for (int k = 0; k < 8; k++) g_lp[(size_t)node * 8 + k] = lg[k] - lse;
        }
    }
}

// ---------------- launch 3 (profiled): edge MLP (unchanged from R9) ----------------
__global__ void __launch_bounds__(256, 2) k_edgemlp(const int* __restrict__ ei,
                                                    const float* __restrict__ w1full,
                                                    const float* __restrict__ b1,
                                                    const float* __restrict__ w2,
                                                    const float* __restrict__ b2) {
    __shared__ uint4  stg[2][512];
    __shared__ uint4  wst[2][128];
    __shared__ float4 epi[64];
    __shared__ float  s1s[256], s2s[256];

    int tid  = threadIdx.x;
    int wid  = tid >> 5;
    int lane = tid & 31;
    int e0   = blockIdx.x * 256;

    uint stgb = smem_u32(stg);
    uint wstb = smem_u32(wst);

    int nsrc = ei[e0 + tid];
    int ndst = ei[EE + e0 + tid];
    const char* pA = (const char*)(g_h16 + (size_t)nsrc * 256);
    const char* pB = (const char*)(g_h16 + (size_t)ndst * 256);
    {
        float a = g_logdeg[nsrc], b = g_logdeg[ndst];
        s1s[tid] = a + b; s2s[tid] = fabsf(a - b);
    }
    if (tid < 64)
        epi[tid] = make_float4(w1full[512 * 64 + tid], w1full[513 * 64 + tid],
                               b1[tid], w2[tid]);
    cpa16(stgb + tid * 16,        pA);
    cpa16(stgb + 4096 + tid * 16, pB);
    if (tid < 128) cpa16(wstb + tid * 16, (const char*)g_Wab16 + tid * 16);
    CPA_COMMIT();

    float acc[2][8][4];
#pragma unroll
    for (int mt = 0; mt < 2; mt++)
#pragma unroll
        for (int t = 0; t < 8; t++)
#pragma unroll
            for (int q = 0; q < 4; q++) acc[mt][t][q] = 0.0f;

    int klane = lane & 15;
    int chi   = lane >> 4;
    int xorv  = lane & 7;
    int r = lane >> 2, c = lane & 3;
    int eb = wid * 32;

    for (int kt = 0; kt < 32; kt++) {
        int buf = kt & 1;
        if (kt < 31) {
            uint db = stgb + (buf ^ 1) * 8192;
            cpa16(db + tid * 16,        pA + (kt + 1) * 16);
            cpa16(db + 4096 + tid * 16, pB + (kt + 1) * 16);
            if (tid < 128)
                cpa16(wstb + (buf ^ 1) * 2048 + tid * 16,
                      (const char*)g_Wab16 + (kt + 1) * 2048 + tid * 16);
            CPA_COMMIT();
            CPA_WAIT1();
        } else {
            CPA_WAIT0();
        }
        __syncthreads();
        const __half* hb = (const __half*)stg + buf * 4096;
        unsigned wbase = wstb + buf * 2048 + (unsigned)(klane * 128);

        unsigned afr[2][4];
#pragma unroll
        for (int mt = 0; mt < 2; mt++) {
            int e1 = eb + mt * 16 + r;
            int e2 = e1 + 8;
            __half hs0 = hb[e1 * 8 + c],      hd0 = hb[2048 + e1 * 8 + c];
            __half hs1 = hb[e2 * 8 + c],      hd1 = hb[2048 + e2 * 8 + c];
            __half hs2 = hb[e1 * 8 + c + 4],  hd2 = hb[2048 + e1 * 8 + c + 4];
            __half hs3 = hb[e2 * 8 + c + 4],  hd3 = hb[2048 + e2 * 8 + c + 4];
            __half2 A0 = __halves2half2(__hmul(hs0, hd0), __habs(__hsub(hs0, hd0)));
            __half2 A1 = __halves2half2(__hmul(hs1, hd1), __habs(__hsub(hs1, hd1)));
            __half2 A2 = __halves2half2(__hmul(hs2, hd2), __habs(__hsub(hs2, hd2)));
            __half2 A3 = __halves2half2(__hmul(hs3, hd3), __habs(__hsub(hs3, hd3)));
            afr[mt][0] = *(unsigned*)&A0; afr[mt][1] = *(unsigned*)&A1;
            afr[mt][2] = *(unsigned*)&A2; afr[mt][3] = *(unsigned*)&A3;
        }
#pragma unroll
        for (int t = 0; t < 4; t++) {
            unsigned b0, b1r, b2r, b3;
            unsigned addr = wbase + (unsigned)((((2 * t + chi) ^ xorv) << 4));
            ldsm4t(b0, b1r, b2r, b3, addr);
#pragma unroll
            for (int mt = 0; mt < 2; mt++) {
                mma16816(acc[mt][2 * t],     afr[mt], b0,  b1r);
                mma16816(acc[mt][2 * t + 1], afr[mt], b2r, b3);
            }
        }
        __syncthreads();
    }

    float b2v = b2[0];
#pragma unroll
    for (int mt = 0; mt < 2; mt++) {
        int er  = eb + mt * 16 + r;
        int er8 = er + 8;
        float s1r = s1s[er], s2r = s2s[er];
        float s18 = s1s[er8], s28 = s2s[er8];
        float vr = 0.0f, v8 = 0.0f;
#pragma unroll
        for (int t = 0; t < 8; t++) {
#pragma unroll
            for (int u = 0; u < 2; u++) {
                float4 pp = epi[t * 8 + c * 2 + u];
                float pre  = acc[mt][t][u]     + s1r * pp.x + s2r * pp.y + pp.z;
                float pre8 = acc[mt][t][2 + u] + s18 * pp.x + s28 * pp.y + pp.z;
                vr += fmaxf(pre, 0.0f) * pp.w;
                v8 += fmaxf(pre8, 0.0f) * pp.w;
            }
        }
        vr += __shfl_xor_sync(0xffffffffu, vr, 1);
        vr += __shfl_xor_sync(0xffffffffu, vr, 2);
        v8 += __shfl_xor_sync(0xffffffffu, v8, 1);
        v8 += __shfl_xor_sync(0xffffffffu, v8, 2);
        if (c == 0) {
            if (e0 + er  < E2n) g_wpre[e0 + er]  = 0.8f / (1.0f + __expf(-(vr + b2v)));
            if (e0 + er8 < E2n) g_wpre[e0 + er8] = 0.8f / (1.0f + __expf(-(v8 + b2v)));
        }
    }
}

// ---------------- launch 4: persistent BP (init + 10 iters + beliefs) ----------------
__device__ __forceinline__ void gridbar(int epoch, int tid) {
    __threadfence();
    __syncthreads();
    if (tid == 0) {
        uint old = atomicAdd(&g_barc, 1u);
        if (old == (uint)(PBLK * epoch - 1)) {
            atomicExch(&g_bars, (uint)epoch);
        } else {
            uint v;
            do {
                asm volatile("ld.global.cg.u32 %0, [%1];" : "=r"(v) : "l"(&g_bars));
            } while (v < (uint)epoch);
        }
    }
    __syncthreads();
}

extern __shared__ char bp_pool[];
__global__ void __launch_bounds__(PTHR, 1) k_bppers(const int* __restrict__ ei,
                                                    const float* __restrict__ mlogit,
                                                    float* __restrict__ out) {
    char* pool = bp_pool;
    uint4*  m_f  = (uint4*)pool;                              // fp16 m fwd [PP]
    uint4*  m_b  = (uint4*)(pool + PP * 16);                  // fp16 m bwd
    uint4*  lf_f = (uint4*)(pool + 2 * PP * 16);              // fp16 logf fwd
    uint4*  lf_b = (uint4*)(pool + 3 * PP * 16);              // fp16 logf bwd
    float2* wen  = (float2*)(pool + 4 * PP * 16);             // (w, en)
    int2*   sdv  = (int2*)(pool + 4 * PP * 16 + PP * 8);      // (s, d)
    float*  Rs   = (float*)(pool + 4 * PP * 16 + 2 * PP * 8);

    int tid = threadIdx.x;
    if (tid < 64) Rs[tid] = g_R[tid];
    __syncthreads();
    int p0 = blockIdx.x * PP;
    float alpha = 1.5f / (1.0f + __expf(-mlogit[0]));

    // ---- init: w, en, m0, logf0, red sumin[0] ----
#pragma unroll 1
    for (int k = 0; k < 6; k++) {
        int pl = tid + k * PTHR;
        int p = p0 + pl;
        if (pl < PP && p < E2n) {
            float w = g_wpre[p];
            int s = ei[p], d = ei[EE + p];
            float en = rsqrtf(fmaxf(g_deg[s], 1.0f) * fmaxf(g_deg[d], 1.0f)) * 0.6931471805599453f;
            wen[pl] = make_float2(w, en);
            sdv[pl] = make_int2(s, d);
            const float4* ls4 = (const float4*)(g_lp + (size_t)s * 8);
            const float4* ld4 = (const float4*)(g_lp + (size_t)d * 8);
            float4 sA = ls4[0], sB = ls4[1], dA = ld4[0], dB = ld4[1];
            float mf[8] = {sA.x, sA.y, sA.z, sA.w, sB.x, sB.y, sB.z, sB.w};
            float mb[8] = {dA.x, dA.y, dA.z, dA.w, dB.x, dB.y, dB.z, dB.w};
            float sf = 0.0f, sb = 0.0f;
#pragma unroll
            for (int c = 0; c < 8; c++) { mf[c] = __expf(mf[c]); sf += mf[c];
                                          mb[c] = __expf(mb[c]); sb += mb[c]; }
            float isf = 1.0f / sf, isb = 1.0f / sb;
#pragma unroll
            for (int c = 0; c < 8; c++) { mf[c] *= isf; mb[c] *= isb; }
            m_f[pl] = pack8h(mf);
            m_b[pl] = pack8h(mb);
            float ff[8] = {0,0,0,0,0,0,0,0}, fb[8] = {0,0,0,0,0,0,0,0};
#pragma unroll
            for (int c = 0; c < 8; c++)
#pragma unroll
                for (int dd = 0; dd < 8; dd++) {
                    float kv = exp2f(w * Rs[c * 8 + dd]);
                    ff[dd] += mf[c] * kv;
                    fb[dd] += mb[c] * kv;
                }
            float lff[8], lfb[8];
#pragma unroll
            for (int i = 0; i < 8; i++) {
                lff[i] = __log2f(fmaxf(ff[i], 1e-12f)) * en;
                lfb[i] = __log2f(fmaxf(fb[i], 1e-12f)) * en;
            }
            lf_f[pl] = pack8h(lff);
            lf_b[pl] = pack8h(lfb);
            float* spd = &g_sumin[0][(size_t)d * 8];
            float* sps = &g_sumin[0][(size_t)s * 8];
            red_add_v4(spd,     lff[0], lff[1], lff[2], lff[3]);
            red_add_v4(spd + 4, lff[4], lff[5], lff[6], lff[7]);
            red_add_v4(sps,     lfb[0], lfb[1], lfb[2], lfb[3]);
            red_add_v4(sps + 4, lfb[4], lfb[5], lfb[6], lfb[7]);
        }
    }
    gridbar(1, tid);

    // ---- 10 BP iterations ----
#pragma unroll 1
    for (int t = 0; t < 10; t++) {
#pragma unroll 1
        for (int k = 0; k < 6; k++) {
            int pl = tid + k * PTHR;
            int p = p0 + pl;
            if (pl < PP && p < E2n) {
                int2 sdl = sdv[pl];
                float2 we = wen[pl];
                int s = sdl.x, d = sdl.y;
                float w = we.x, en = we.y;
                float4 sisA = ldcg4(g_sumin[t] + (size_t)s * 8);
                float4 sisB = ldcg4(g_sumin[t] + (size_t)s * 8 + 4);
                float4 sidA = ldcg4(g_sumin[t] + (size_t)d * 8);
                float4 sidB = ldcg4(g_sumin[t] + (size_t)d * 8 + 4);
                const float4* ls4 = (const float4*)(g_lp + (size_t)s * 8);
                const float4* ld4 = (const float4*)(g_lp + (size_t)d * 8);
                float4 lsA = ls4[0], lsB = ls4[1], ldA = ld4[0], ldB = ld4[1];
                float sis[8] = {sisA.x, sisA.y, sisA.z, sisA.w, sisB.x, sisB.y, sisB.z, sisB.w};
                float sid[8] = {sidA.x, sidA.y, sidA.z, sidA.w, sidB.x, sidB.y, sidB.z, sidB.w};
                float lps[8] = {lsA.x, lsA.y, lsA.z, lsA.w, lsB.x, lsB.y, lsB.z, lsB.w};
                float lpd[8] = {ldA.x, ldA.y, ldA.z, ldA.w, ldB.x, ldB.y, ldB.z, ldB.w};
                float lfp[8], lbp[8];
                unpack8h(lf_f[pl], lfp);
                unpack8h(lf_b[pl], lbp);

                float tf[8], tb[8], mxf = -1e30f, mxb = -1e30f;
#pragma unroll
                for (int i = 0; i < 8; i++) {
                    tf[i] = lps[i] + alpha * (sis[i] - lbp[i]);
                    tb[i] = lpd[i] + alpha * (sid[i] - lfp[i]);
                    mxf = fmaxf(mxf, tf[i]); mxb = fmaxf(mxb, tb[i]);
                }
                float ssf = 0.0f, ssb = 0.0f;
#pragma unroll
                for (int i = 0; i < 8; i++) {
                    tf[i] = __expf(tf[i] - mxf); ssf += tf[i];
                    tb[i] = __expf(tb[i] - mxb); ssb += tb[i];
                }
                float ivf = 0.2f / ssf, ivb = 0.2f / ssb;
                float mf[8], mb[8];
                unpack8h(m_f[pl], mf);
                unpack8h(m_b[pl], mb);
                float s2f = 0.0f, s2b = 0.0f;
#pragma unroll
                for (int i = 0; i < 8; i++) {
                    mf[i] = fmaxf(0.8f * mf[i] + tf[i] * ivf, 1e-12f); s2f += mf[i];
                    mb[i] = fmaxf(0.8f * mb[i] + tb[i] * ivb, 1e-12f); s2b += mb[i];
                }
                float i2f = 1.0f / s2f, i2b = 1.0f / s2b;
#pragma unroll
                for (int i = 0; i < 8; i++) { mf[i] *= i2f; mb[i] *= i2b; }
                m_f[pl] = pack8h(mf);
                m_b[pl] = pack8h(mb);

                float ff[8] = {0,0,0,0,0,0,0,0}, fb[8] = {0,0,0,0,0,0,0,0};
#pragma unroll
                for (int c = 0; c < 8; c++)
#pragma unroll
                    for (int dd = 0; dd < 8; dd++) {
                        float kv = exp2f(w * Rs[c * 8 + dd]);
                        ff[dd] += mf[c] * kv;
                        fb[dd] += mb[c] * kv;
                    }
                float lff[8], lfb2[8];
#pragma unroll
                for (int i = 0; i < 8; i++) {
                    lff[i]  = __log2f(fmaxf(ff[i], 1e-12f)) * en;
                    lfb2[i] = __log2f(fmaxf(fb[i], 1e-12f)) * en;
                }
                lf_f[pl] = pack8h(lff);
                lf_b[pl] = pack8h(lfb2);
                float* spd = &g_sumin[t + 1][(size_t)d * 8];
                float* sps = &g_sumin[t + 1][(size_t)s * 8];
                red_add_v4(spd,     lff[0], lff[1], lff[2], lff[3]);
                red_add_v4(spd + 4, lff[4], lff[5], lff[6], lff[7]);
                red_add_v4(sps,     lfb2[0], lfb2[1], lfb2[2], lfb2[3]);
                red_add_v4(sps + 4, lfb2[4], lfb2[5], lfb2[6], lfb2[7]);
            }
        }
        gridbar(t + 2, tid);
    }

    // ---- beliefs: 338 nodes per block ----
    int n = blockIdx.x * 338 + tid;
    if (tid < 338 && n < NN) {
        float tt[8], mx = -1e30f;
        float4 siA = ldcg4(g_sumin[10] + (size_t)n * 8);
        float4 siB = ldcg4(g_sumin[10] + (size_t)n * 8 + 4);
        float si[8] = {siA.x, siA.y, siA.z, siA.w, siB.x, siB.y, siB.z, siB.w};
#pragma unroll
        for (int c = 0; c < 8; c++) {
            tt[c] = g_lp[(size_t)n * 8 + c] + alpha * si[c];
            mx = fmaxf(mx, tt[c]);
        }
        float sum = 0.0f;
#pragma unroll
        for (int c = 0; c < 8; c++) { tt[c] = __expf(tt[c] - mx); sum += tt[c]; }
        float inv = 1.0f / sum;
#pragma unroll
        for (int c = 0; c < 8; c++) out[(size_t)n * 8 + c] = tt[c] * inv;
    }
}

// ---------------- launch ----------------
extern "C" void kernel_launch(void* const* d_in, const int* in_sizes, int n_in,
                              void* d_out, int out_size) {
    const float* x       = (const float*)d_in[0];
    const int*   ei      = (const int*)d_in[1];
    const float* enc_w1  = (const float*)d_in[3];
    const float* enc_b1  = (const float*)d_in[4];
    const float* enc_w2  = (const float*)d_in[5];
    const float* enc_b2  = (const float*)d_in[6];
    const float* edge_w1 = (const float*)d_in[7];
    const float* edge_b1 = (const float*)d_in[8];
    const float* edge_w2 = (const float*)d_in[9];
    const float* edge_b2 = (const float*)d_in[10];
    const float* R_raw   = (const float*)d_in[11];
    const float* rsl     = (const float*)d_in[12];
    const float* mlogit  = (const float*)d_in[13];
    float* out = (float*)d_out;

    cudaFuncSetAttribute(k_encoder, cudaFuncAttributeMaxDynamicSharedMemorySize, 40960);
    // 4*PP*16 + 2*PP*8 + 256 = 216496 -> request rounded up
    cudaFuncSetAttribute(k_bppers, cudaFuncAttributeMaxDynamicSharedMemorySize, 216576);

    int PB = (E2n + 255) / 256;

    k_prep_all<<<(11 * NN * 8 + 255) / 256, 256>>>(R_raw, rsl, edge_w1, enc_w1); // 0
    k_deg<<<(EE + 255) / 256, 256>>>(ei);                                        // 1
    k_encoder<<<(NN + 63) / 64, 256, 40960>>>(x, enc_b1, enc_w2, enc_b2);        // 2 (+logdeg)
    k_edgemlp<<<PB, 256>>>(ei, edge_w1, edge_b1, edge_w2, edge_b2);              // 3 <- profiled
    k_bppers<<<PBLK, PTHR, 216576>>>(ei, mlogit, out);                           // 4 (init+10 iters+beliefs)
}

// round 11
// speedup vs baseline: 1.1053x; 1.1053x over previous
#include <cuda_runtime.h>
#include <cuda_fp16.h>
#include <math.h>

#define NN   50000
#define E2n  400000
#define EE   800000

typedef unsigned long long ull;
typedef unsigned int uint;

// ---------------- scratch ----------------
__device__ __align__(16) __half g_h16[(size_t)NN * 256];     // 25.6 MB
__device__ __align__(16) float g_lp[(size_t)NN * 8];
__device__ float g_deg[NN];
__device__ float g_logdeg[NN];
__device__ float g_wpre[E2n];
__device__ float g_w[E2n];
__device__ float g_enorm[E2n];                               // rsqrt(..)*ln2
__device__ __align__(16) __half g_m16[(size_t)EE * 8];       // fp16 messages, 12.8 MB
__device__ __align__(16) __half g_logf16[2][(size_t)EE * 8]; // 2 x 12.8 MB
__device__ __align__(32) float g_sumin[11][(size_t)NN * 8];  // pre-zeroed
__device__ __align__(16) float g_R[64];                      // R * log2(e)
__device__ __align__(16) __half g_Wab16[512 * 64];           // edge_w1 interleaved+swizzled
__device__ __align__(16) __half g_w1h[512 * 256];            // enc_w1 hi
__device__ __align__(16) __half g_w1l[512 * 256];            // enc_w1 lo residual

// ---------------- helpers ----------------
__device__ __forceinline__ void red_add_v4(float* p, float a, float b, float c, float d) {
    ull gp = (ull)__cvta_generic_to_global(p);
    asm volatile("red.global.add.v4.f32 [%0], {%1,%2,%3,%4};"
                 :: "l"(gp), "f"(a), "f"(b), "f"(c), "f"(d) : "memory");
}
__device__ __forceinline__ unsigned smem_u32(const void* p) {
    unsigned a;
    asm("{ .reg .u64 t; cvta.to.shared.u64 t, %1; cvt.u32.u64 %0, t; }" : "=r"(a) : "l"(p));
    return a;
}
__device__ __forceinline__ void cpa16(uint saddr, const void* g) {
    asm volatile("cp.async.cg.shared.global [%0], [%1], 16;" :: "r"(saddr), "l"(g));
}
#define CPA_COMMIT() asm volatile("cp.async.commit_group;")
#define CPA_WAIT1()  asm volatile("cp.async.wait_group 1;")
#define CPA_WAIT0()  asm volatile("cp.async.wait_group 0;")
__device__ __forceinline__ void ldsm4(uint& a, uint& b, uint& c, uint& d, uint addr) {
    asm volatile("ldmatrix.sync.aligned.m8n8.x4.shared.b16 {%0,%1,%2,%3}, [%4];"
                 : "=r"(a), "=r"(b), "=r"(c), "=r"(d) : "r"(addr));
}
__device__ __forceinline__ void ldsm4t(uint& a, uint& b, uint& c, uint& d, uint addr) {
    asm volatile("ldmatrix.sync.aligned.m8n8.x4.trans.shared.b16 {%0,%1,%2,%3}, [%4];"
                 : "=r"(a), "=r"(b), "=r"(c), "=r"(d) : "r"(addr));
}
__device__ __forceinline__ void mma16816(float* acc, const uint* a, uint b0, uint b1) {
    asm volatile("mma.sync.aligned.m16n8k16.row.col.f32.f16.f16.f32 "
                 "{%0,%1,%2,%3}, {%4,%5,%6,%7}, {%8,%9}, {%0,%1,%2,%3};"
                 : "+f"(acc[0]), "+f"(acc[1]), "+f"(acc[2]), "+f"(acc[3])
                 : "r"(a[0]), "r"(a[1]), "r"(a[2]), "r"(a[3]), "r"(b0), "r"(b1));
}
__device__ __forceinline__ uint4 pack8h(const float* v) {
    __half2 a = __floats2half2_rn(v[0], v[1]);
    __half2 b = __floats2half2_rn(v[2], v[3]);
    __half2 c = __floats2half2_rn(v[4], v[5]);
    __half2 d = __floats2half2_rn(v[6], v[7]);
    return make_uint4(*(uint*)&a, *(uint*)&b, *(uint*)&c, *(uint*)&d);
}
__device__ __forceinline__ void unpack8h(uint4 u, float* v) {
    float2 a = __half22float2(*(__half2*)&u.x);
    float2 b = __half22float2(*(__half2*)&u.y);
    float2 c = __half22float2(*(__half2*)&u.z);
    float2 d = __half22float2(*(__half2*)&u.w);
    v[0] = a.x; v[1] = a.y; v[2] = b.x; v[3] = b.y;
    v[4] = c.x; v[5] = c.y; v[6] = d.x; v[7] = d.y;
}

// ---------------- launch 0: prep ----------------
__global__ void k_prep_all(const float* __restrict__ R_raw, const float* __restrict__ rsl,
                           const float* __restrict__ ew1, const float* __restrict__ encw1) {
    int i = blockIdx.x * 256 + threadIdx.x;
    if (i < 11 * NN * 8) ((float*)g_sumin)[i] = 0.0f;
    if (i < NN) g_deg[i] = 0.0f;
    if (i < 512 * 64) {
        int k = i >> 6, j = i & 63;
        int c = j >> 3, u = j & 7;
        int pos = (k << 6) + (((c ^ (k & 7)) << 3) + u);
        int hc = k >> 1;
        float v = (k & 1) ? ew1[(256 + hc) * 64 + j] : ew1[hc * 64 + j];
        g_Wab16[pos] = __float2half_rn(v);
    }
    if (i < 512 * 256) {
        float v = encw1[i];
        __half h = __float2half_rn(v);
        g_w1h[i] = h;
        g_w1l[i] = __float2half_rn(v - __half2float(h));
    }
    if (i < 64) {
        int r = i >> 3, c = i & 7;
        float v = 0.5f * (R_raw[r * 8 + c] + R_raw[c * 8 + r]);
        float s = log1pf(expf(rsl[0])) + 1e-6f;
        g_R[i] = s * tanhf(v) * 1.44269504088896f;
    }
}

// ---------------- launch 1: degree ----------------
__global__ void k_deg(const int* __restrict__ ei) {
    int e = blockIdx.x * blockDim.x + threadIdx.x;
    if (e < EE) atomicAdd(&g_deg[ei[e]], 1.0f);
}

// ---------------- launch 2: encoder (split-fp16 HMMA, cp.async weights) + logdeg + logits ----------------
extern __shared__ char enc_pool[];
__global__ void __launch_bounds__(256, 2) k_encoder(const float* __restrict__ x,
                                                    const float* __restrict__ b1,
                                                    const float* __restrict__ w2,
                                                    const float* __restrict__ b2) {
    __shared__ float w2s[256][8];
    __shared__ float b1s[256];
    __shared__ float slog[64][8];
    char* pool = enc_pool;
    uint pbase = smem_u32(pool);
    int tid = threadIdx.x, lane = tid & 31, wid = tid >> 5;
    int mw = wid & 3, nw = wid >> 2;

    if (blockIdx.x < (NN + 255) / 256) {
        int n = blockIdx.x * 256 + tid;
        if (n < NN) g_logdeg[n] = __logf(g_deg[n] + 1.0f);
    }
    for (int i = tid; i < 2048; i += 256) w2s[i >> 3][i & 7] = w2[i];
    if (tid < 256) b1s[tid] = b1[tid];
    for (int i = tid; i < 512; i += 256) ((float*)slog)[i] = 0.0f;

    int n0 = blockIdx.x * 64;

    auto stageA = [&](int kt, int buf) {
        if (tid < 128) {
            int r = tid >> 1, c = tid & 1;
            int gn = min(n0 + r, NN - 1);
            const float4* xr = (const float4*)x + (size_t)gn * 128 + kt * 4 + c * 2;
            float4 f0 = xr[0], f1 = xr[1];
            float v[8] = {f0.x, f0.y, f0.z, f0.w, f1.x, f1.y, f1.z, f1.w};
            __half hi[8], lo[8];
#pragma unroll
            for (int q = 0; q < 8; q++) {
                __half h = __float2half_rn(v[q]);
                hi[q] = h;
                lo[q] = __float2half_rn(v[q] - __half2float(h));
            }
            int cp = c ^ ((r >> 2) & 1);
            *(uint4*)(pool + (buf * 2 + 0) * 2048 + r * 32 + cp * 16) = *(uint4*)hi;
            *(uint4*)(pool + (buf * 2 + 1) * 2048 + r * 32 + cp * 16) = *(uint4*)lo;
        }
    };
    auto stageB = [&](int kt, int buf) {
#pragma unroll
        for (int q = 0; q < 4; q++) {
            int id = tid + 256 * q;
            int which = id >> 9, rem = id & 511, k = rem >> 5, cu = rem & 31;
            const char* src = (const char*)(which ? g_w1l : g_w1h)
                              + (((size_t)(kt * 16 + k) * 32 + cu) << 4);
            int cp = cu ^ (k & 7);
            cpa16(pbase + 8192 + (buf * 2 + which) * 8192 + k * 512 + cp * 16, src);
        }
    };

    stageA(0, 0); stageB(0, 0); CPA_COMMIT();

    float acc[16][4];
#pragma unroll
    for (int t = 0; t < 16; t++)
#pragma unroll
        for (int q = 0; q < 4; q++) acc[t][q] = 0.0f;

    int q4 = lane >> 3, l8 = lane & 7;
    int arow = mw * 16 + (q4 & 1) * 8 + l8;
    uint aoff = (uint)(arow * 32 + (((q4 >> 1) ^ ((arow >> 2) & 1)) * 16));
    int bk = lane & 15, chi = lane >> 4;
    uint bko = (uint)(bk * 512);

    for (int kt = 0; kt < 32; kt++) {
        int buf = kt & 1;
        if (kt < 31) {
            stageA(kt + 1, buf ^ 1); stageB(kt + 1, buf ^ 1); CPA_COMMIT();
            CPA_WAIT1();
        } else {
            CPA_WAIT0();
        }
        __syncthreads();
        uint a1b = pbase + (buf * 2 + 0) * 2048 + aoff;
        uint a2b = pbase + (buf * 2 + 1) * 2048 + aoff;
        uint bhb = pbase + 8192 + (buf * 2 + 0) * 8192 + bko;
        uint blb = pbase + 8192 + (buf * 2 + 1) * 8192 + bko;
        uint A1[4], A2[4];
        ldsm4(A1[0], A1[1], A1[2], A1[3], a1b);
        ldsm4(A2[0], A2[1], A2[2], A2[3], a2b);
#pragma unroll
        for (int t = 0; t < 8; t++) {
            int chunk = nw * 16 + t * 2 + chi;
            uint coff = (uint)((chunk ^ (bk & 7)) * 16);
            uint h0, h1, h2, h3, l0, l1, l2, l3;
            ldsm4t(h0, h1, h2, h3, bhb + coff);
            ldsm4t(l0, l1, l2, l3, blb + coff);
            mma16816(acc[2 * t],     A1, h0, h1);
            mma16816(acc[2 * t + 1], A1, h2, h3);
            mma16816(acc[2 * t],     A1, l0, l1);
            mma16816(acc[2 * t + 1], A1, l2, l3);
            mma16816(acc[2 * t],     A2, h0, h1);
            mma16816(acc[2 * t + 1], A2, h2, h3);
        }
        __syncthreads();
    }

    int r = lane >> 2, c = lane & 3;
    int row0 = mw * 16 + r;
    float pl0[8], pl1[8];
#pragma unroll
    for (int k = 0; k < 8; k++) { pl0[k] = 0.0f; pl1[k] = 0.0f; }
    __half* h16s = (__half*)pool;
#pragma unroll
    for (int tt = 0; tt < 16; tt++) {
        int j0 = nw * 128 + tt * 8 + 2 * c;
        float hv0 = fmaxf(acc[tt][0] + b1s[j0],     0.0f);
        float hv1 = fmaxf(acc[tt][1] + b1s[j0 + 1], 0.0f);
        float hv2 = fmaxf(acc[tt][2] + b1s[j0],     0.0f);
        float hv3 = fmaxf(acc[tt][3] + b1s[j0 + 1], 0.0f);
        *(__half2*)(h16s + row0 * 264 + j0)       = __floats2half2_rn(hv0, hv1);
        *(__half2*)(h16s + (row0 + 8) * 264 + j0) = __floats2half2_rn(hv2, hv3);
        const float4* w2a = (const float4*)w2s[j0];
        const float4* w2b = (const float4*)w2s[j0 + 1];
        float4 a0 = w2a[0], a1 = w2a[1], b0 = w2b[0], b1v = w2b[1];
        pl0[0] += hv0 * a0.x + hv1 * b0.x;  pl0[1] += hv0 * a0.y + hv1 * b0.y;
        pl0[2] += hv0 * a0.z + hv1 * b0.z;  pl0[3] += hv0 * a0.w + hv1 * b0.w;
        pl0[4] += hv0 * a1.x + hv1 * b1v.x; pl0[5] += hv0 * a1.y + hv1 * b1v.y;
        pl0[6] += hv0 * a1.z + hv1 * b1v.z; pl0[7] += hv0 * a1.w + hv1 * b1v.w;
        pl1[0] += hv2 * a0.x + hv3 * b0.x;  pl1[1] += hv2 * a0.y + hv3 * b0.y;
        pl1[2] += hv2 * a0.z + hv3 * b0.z;  pl1[3] += hv2 * a0.w + hv3 * b0.w;
        pl1[4] += hv2 * a1.x + hv3 * b1v.x; pl1[5] += hv2 * a1.y + hv3 * b1v.y;
        pl1[6] += hv2 * a1.z + hv3 * b1v.z; pl1[7] += hv2 * a1.w + hv3 * b1v.w;
    }
#pragma unroll
    for (int k = 0; k < 8; k++) {
        pl0[k] += __shfl_xor_sync(0xffffffffu, pl0[k], 1);
        pl0[k] += __shfl_xor_sync(0xffffffffu, pl0[k], 2);
        pl1[k] += __shfl_xor_sync(0xffffffffu, pl1[k], 1);
        pl1[k] += __shfl_xor_sync(0xffffffffu, pl1[k], 2);
    }
    if (c == 0) {
#pragma unroll
        for (int k = 0; k < 8; k++) {
            atomicAdd(&slog[row0][k], pl0[k]);
            atomicAdd(&slog[row0 + 8][k], pl1[k]);
        }
    }
    __syncthreads();
#pragma unroll
    for (int i = 0; i < 8; i++) {
        int id = tid + 256 * i;
        int row = id >> 5, cu = id & 31;
        int node = n0 + row;
        if (node < NN) {
            uint4 v = ((uint4*)pool)[row * 33 + cu];
            ((uint4*)g_h16)[(size_t)node * 32 + cu] = v;
        }
    }
    if (tid < 64) {
        int node = n0 + tid;
        if (node < NN) {
            float lg[8], mx = -1e30f;
#pragma unroll
            for (int k = 0; k < 8; k++) { lg[k] = slog[tid][k] + b2[k]; mx = fmaxf(mx, lg[k]); }
            float s = 0.0f;
#pragma unroll
            for (int k = 0; k < 8; k++) s += __expf(lg[k] - mx);
            float lse = mx + __logf(s);
#pragma unroll
            for (int k = 0; k < 8; k++) g_lp[(size_t)node * 8 + k] = lg[k] - lse;
        }
    }
}

// ---------------- launch 3 (profiled): edge MLP, cp.async gathers ----------------
__global__ void __launch_bounds__(256, 2) k_edgemlp(const int* __restrict__ ei,
                                                    const float* __restrict__ w1full,
                                                    const float* __restrict__ b1,
                                                    const float* __restrict__ w2,
                                                    const float* __restrict__ b2) {
    __shared__ uint4  stg[2][512];
    __shared__ uint4  wst[2][128];
    __shared__ float4 epi[64];
    __shared__ float  s1s[256], s2s[256];

    int tid  = threadIdx.x;
    int wid  = tid >> 5;
    int lane = tid & 31;
    int e0   = blockIdx.x * 256;

    uint stgb = smem_u32(stg);
    uint wstb = smem_u32(wst);

    int nsrc = ei[e0 + tid];
    int ndst = ei[EE + e0 + tid];
    const char* pA = (const char*)(g_h16 + (size_t)nsrc * 256);
    const char* pB = (const char*)(g_h16 + (size_t)ndst * 256);
    {
        float a = g_logdeg[nsrc], b = g_logdeg[ndst];
        s1s[tid] = a + b; s2s[tid] = fabsf(a - b);
    }
    if (tid < 64)
        epi[tid] = make_float4(w1full[512 * 64 + tid], w1full[513 * 64 + tid],
                               b1[tid], w2[tid]);
    cpa16(stgb + tid * 16,        pA);
    cpa16(stgb + 4096 + tid * 16, pB);
    if (tid < 128) cpa16(wstb + tid * 16, (const char*)g_Wab16 + tid * 16);
    CPA_COMMIT();

    float acc[2][8][4];
#pragma unroll
    for (int mt = 0; mt < 2; mt++)
#pragma unroll
        for (int t = 0; t < 8; t++)
#pragma unroll
            for (int q = 0; q < 4; q++) acc[mt][t][q] = 0.0f;

    int klane = lane & 15;
    int chi   = lane >> 4;
    int xorv  = lane & 7;
    int r = lane >> 2, c = lane & 3;
    int eb = wid * 32;

    for (int kt = 0; kt < 32; kt++) {
        int buf = kt & 1;
        if (kt < 31) {
            uint db = stgb + (buf ^ 1) * 8192;
            cpa16(db + tid * 16,        pA + (kt + 1) * 16);
            cpa16(db + 4096 + tid * 16, pB + (kt + 1) * 16);
            if (tid < 128)
                cpa16(wstb + (buf ^ 1) * 2048 + tid * 16,
                      (const char*)g_Wab16 + (kt + 1) * 2048 + tid * 16);
            CPA_COMMIT();
            CPA_WAIT1();
        } else {
            CPA_WAIT0();
        }
        __syncthreads();
        const __half* hb = (const __half*)stg + buf * 4096;
        unsigned wbase = wstb + buf * 2048 + (unsigned)(klane * 128);

        unsigned afr[2][4];
#pragma unroll
        for (int mt = 0; mt < 2; mt++) {
            int e1 = eb + mt * 16 + r;
            int e2 = e1 + 8;
            __half hs0 = hb[e1 * 8 + c],      hd0 = hb[2048 + e1 * 8 + c];
            __half hs1 = hb[e2 * 8 + c],      hd1 = hb[2048 + e2 * 8 + c];
            __half hs2 = hb[e1 * 8 + c + 4],  hd2 = hb[2048 + e1 * 8 + c + 4];
            __half hs3 = hb[e2 * 8 + c + 4],  hd3 = hb[2048 + e2 * 8 + c + 4];
            __half2 A0 = __halves2half2(__hmul(hs0, hd0), __habs(__hsub(hs0, hd0)));
            __half2 A1 = __halves2half2(__hmul(hs1, hd1), __habs(__hsub(hs1, hd1)));
            __half2 A2 = __halves2half2(__hmul(hs2, hd2), __habs(__hsub(hs2, hd2)));
            __half2 A3 = __halves2half2(__hmul(hs3, hd3), __habs(__hsub(hs3, hd3)));
            afr[mt][0] = *(unsigned*)&A0; afr[mt][1] = *(unsigned*)&A1;
            afr[mt][2] = *(unsigned*)&A2; afr[mt][3] = *(unsigned*)&A3;
        }
#pragma unroll
        for (int t = 0; t < 4; t++) {
            unsigned b0, b1r, b2r, b3;
            unsigned addr = wbase + (unsigned)((((2 * t + chi) ^ xorv) << 4));
            ldsm4t(b0, b1r, b2r, b3, addr);
#pragma unroll
            for (int mt = 0; mt < 2; mt++) {
                mma16816(acc[mt][2 * t],     afr[mt], b0,  b1r);
                mma16816(acc[mt][2 * t + 1], afr[mt], b2r, b3);
            }
        }
        __syncthreads();
    }

    float b2v = b2[0];
#pragma unroll
    for (int mt = 0; mt < 2; mt++) {
        int er  = eb + mt * 16 + r;
        int er8 = er + 8;
        float s1r = s1s[er], s2r = s2s[er];
        float s18 = s1s[er8], s28 = s2s[er8];
        float vr = 0.0f, v8 = 0.0f;
#pragma unroll
        for (int t = 0; t < 8; t++) {
#pragma unroll
            for (int u = 0; u < 2; u++) {
                float4 pp = epi[t * 8 + c * 2 + u];
                float pre  = acc[mt][t][u]     + s1r * pp.x + s2r * pp.y + pp.z;
                float pre8 = acc[mt][t][2 + u] + s18 * pp.x + s28 * pp.y + pp.z;
                vr += fmaxf(pre, 0.0f) * pp.w;
                v8 += fmaxf(pre8, 0.0f) * pp.w;
            }
        }
        vr += __shfl_xor_sync(0xffffffffu, vr, 1);
        vr += __shfl_xor_sync(0xffffffffu, vr, 2);
        v8 += __shfl_xor_sync(0xffffffffu, v8, 1);
        v8 += __shfl_xor_sync(0xffffffffu, v8, 2);
        if (c == 0) {
            if (e0 + er  < E2n) g_wpre[e0 + er]  = 0.8f / (1.0f + __expf(-(vr + b2v)));
            if (e0 + er8 < E2n) g_wpre[e0 + er8] = 0.8f / (1.0f + __expf(-(v8 + b2v)));
        }
    }
}

// ---------------- launch 4: pair init + first A phase ----------------
__global__ void __launch_bounds__(256) k_initA(const int* __restrict__ ei) {
    __shared__ float Rs[64];
    if (threadIdx.x < 64) Rs[threadIdx.x] = g_R[threadIdx.x];
    __syncthreads();
    int p = blockIdx.x * 256 + threadIdx.x;
    if (p >= E2n) return;
    float w = g_wpre[p];
    g_w[p] = w;
    int s = ei[p], d = ei[EE + p];
    float en = rsqrtf(fmaxf(g_deg[s], 1.0f) * fmaxf(g_deg[d], 1.0f)) * 0.6931471805599453f;
    g_enorm[p] = en;
    const float4* ls4 = (const float4*)(g_lp + (size_t)s * 8);
    const float4* ld4 = (const float4*)(g_lp + (size_t)d * 8);
    float4 sA = ls4[0], sB = ls4[1], dA = ld4[0], dB = ld4[1];
    float mf[8] = {sA.x, sA.y, sA.z, sA.w, sB.x, sB.y, sB.z, sB.w};
    float mb[8] = {dA.x, dA.y, dA.z, dA.w, dB.x, dB.y, dB.z, dB.w};
    float sf = 0.0f, sb = 0.0f;
#pragma unroll
    for (int c = 0; c < 8; c++) { mf[c] = __expf(mf[c]); sf += mf[c];
                                  mb[c] = __expf(mb[c]); sb += mb[c]; }
    float isf = 1.0f / sf, isb = 1.0f / sb;
#pragma unroll
    for (int c = 0; c < 8; c++) { mf[c] *= isf; mb[c] *= isb; }
    ((uint4*)g_m16)[p]       = pack8h(mf);
    ((uint4*)g_m16)[p + E2n] = pack8h(mb);
    float ff[8] = {0,0,0,0,0,0,0,0}, fb[8] = {0,0,0,0,0,0,0,0};
#pragma unroll
    for (int c = 0; c < 8; c++)
#pragma unroll
        for (int dd = 0; dd < 8; dd++) {
            float kv = exp2f(w * Rs[c * 8 + dd]);
            ff[dd] += mf[c] * kv;
            fb[dd] += mb[c] * kv;
        }
    float lff[8], lfb[8];
#pragma unroll
    for (int i = 0; i < 8; i++) {
        lff[i] = __log2f(fmaxf(ff[i], 1e-12f)) * en;
        lfb[i] = __log2f(fmaxf(fb[i], 1e-12f)) * en;
    }
    ((uint4*)g_logf16[0])[p]       = pack8h(lff);
    ((uint4*)g_logf16[0])[p + E2n] = pack8h(lfb);
    float* spd = &g_sumin[0][(size_t)d * 8];
    float* sps = &g_sumin[0][(size_t)s * 8];
    red_add_v4(spd,     lff[0], lff[1], lff[2], lff[3]);
    red_add_v4(spd + 4, lff[4], lff[5], lff[6], lff[7]);
    red_add_v4(sps,     lfb[0], lfb[1], lfb[2], lfb[3]);
    red_add_v4(sps + 4, lfb[4], lfb[5], lfb[6], lfb[7]);
}

// ---------------- BP step t (pairs): B(t) then A(t+1) ----------------
__global__ void __launch_bounds__(256) k_bp(const int* __restrict__ ei,
                                            const float* __restrict__ mlogit, int t) {
    __shared__ float Rs[64];
    if (threadIdx.x < 64) Rs[threadIdx.x] = g_R[threadIdx.x];
    __syncthreads();
    int p = blockIdx.x * 256 + threadIdx.x;
    if (p >= E2n) return;
    int pr = t & 1;
    float alpha = 1.5f / (1.0f + __expf(-mlogit[0]));
    int s = ei[p], d = ei[EE + p];
    float w = g_w[p], en = g_enorm[p];
    const float4* sis4 = (const float4*)(g_sumin[t] + (size_t)s * 8);
    const float4* sid4 = (const float4*)(g_sumin[t] + (size_t)d * 8);
    const float4* ls4  = (const float4*)(g_lp + (size_t)s * 8);
    const float4* ld4  = (const float4*)(g_lp + (size_t)d * 8);
    uint4 vlf = ((const uint4*)g_logf16[pr])[p];
    uint4 vlb = ((const uint4*)g_logf16[pr])[p + E2n];
    uint4 vmf = ((const uint4*)g_m16)[p];
    uint4 vmb = ((const uint4*)g_m16)[p + E2n];

    float4 sisA = sis4[0], sisB = sis4[1], sidA = sid4[0], sidB = sid4[1];
    float4 lsA = ls4[0], lsB = ls4[1], ldA = ld4[0], ldB = ld4[1];
    float sis[8] = {sisA.x, sisA.y, sisA.z, sisA.w, sisB.x, sisB.y, sisB.z, sisB.w};
    float sid[8] = {sidA.x, sidA.y, sidA.z, sidA.w, sidB.x, sidB.y, sidB.z, sidB.w};
    float lps[8] = {lsA.x, lsA.y, lsA.z, lsA.w, lsB.x, lsB.y, lsB.z, lsB.w};
    float lpd[8] = {ldA.x, ldA.y, ldA.z, ldA.w, ldB.x, ldB.y, ldB.z, ldB.w};
    float lfp[8], lbp[8];
    unpack8h(vlf, lfp);
    unpack8h(vlb, lbp);

    float tf[8], tb[8], mxf = -1e30f, mxb = -1e30f;
#pragma unroll
    for (int i = 0; i < 8; i++) {
        tf[i] = lps[i] + alpha * (sis[i] - lbp[i]);
        tb[i] = lpd[i] + alpha * (sid[i] - lfp[i]);
        mxf = fmaxf(mxf, tf[i]); mxb = fmaxf(mxb, tb[i]);
    }
    float ssf = 0.0f, ssb = 0.0f;
#pragma unroll
    for (int i = 0; i < 8; i++) {
        tf[i] = __expf(tf[i] - mxf); ssf += tf[i];
        tb[i] = __expf(tb[i] - mxb); ssb += tb[i];
    }
    float ivf = 0.2f / ssf, ivb = 0.2f / ssb;
    float mf[8], mb[8];
    unpack8h(vmf, mf);
    unpack8h(vmb, mb);
    float s2f = 0.0f, s2b = 0.0f;
#pragma unroll
    for (int i = 0; i < 8; i++) {
        mf[i] = fmaxf(0.8f * mf[i] + tf[i] * ivf, 1e-12f); s2f += mf[i];
        mb[i] = fmaxf(0.8f * mb[i] + tb[i] * ivb, 1e-12f); s2b += mb[i];
    }
    float i2f = 1.0f / s2f, i2b = 1.0f / s2b;
#pragma unroll
    for (int i = 0; i < 8; i++) { mf[i] *= i2f; mb[i] *= i2b; }
    ((uint4*)g_m16)[p]       = pack8h(mf);
    ((uint4*)g_m16)[p + E2n] = pack8h(mb);

    float ff[8] = {0,0,0,0,0,0,0,0}, fb[8] = {0,0,0,0,0,0,0,0};
#pragma unroll
    for (int c = 0; c < 8; c++)
#pragma unroll
        for (int dd = 0; dd < 8; dd++) {
            float kv = exp2f(w * Rs[c * 8 + dd]);
            ff[dd] += mf[c] * kv;
            fb[dd] += mb[c] * kv;
        }
    float lff[8], lfb[8];
#pragma unroll
    for (int i = 0; i < 8; i++) {
        lff[i] = __log2f(fmaxf(ff[i], 1e-12f)) * en;
        lfb[i] = __log2f(fmaxf(fb[i], 1e-12f)) * en;
    }
    ((uint4*)g_logf16[pr ^ 1])[p]       = pack8h(lff);
    ((uint4*)g_logf16[pr ^ 1])[p + E2n] = pack8h(lfb);
    float* spd = &g_sumin[t + 1][(size_t)d * 8];
    float* sps = &g_sumin[t + 1][(size_t)s * 8];
    red_add_v4(spd,     lff[0], lff[1], lff[2], lff[3]);
    red_add_v4(spd + 4, lff[4], lff[5], lff[6], lff[7]);
    red_add_v4(sps,     lfb[0], lfb[1], lfb[2], lfb[3]);
    red_add_v4(sps + 4, lfb[4], lfb[5], lfb[6], lfb[7]);
}

// ---------------- final beliefs ----------------
__global__ void k_belief(const float* __restrict__ mlogit, float* __restrict__ out) {
    int n = blockIdx.x * blockDim.x + threadIdx.x;
    if (n >= NN) return;
    float alpha = 1.5f / (1.0f + __expf(-mlogit[0]));
    float t[8], mx = -1e30f;
#pragma unroll
    for (int c = 0; c < 8; c++) {
        t[c] = g_lp[(size_t)n * 8 + c] + alpha * g_sumin[10][(size_t)n * 8 + c];
        mx = fmaxf(mx, t[c]);
    }
    float sum = 0.0f;
#pragma unroll
    for (int c = 0; c < 8; c++) { t[c] = __expf(t[c] - mx); sum += t[c]; }
    float inv = 1.0f / sum;
#pragma unroll
    for (int c = 0; c < 8; c++) out[(size_t)n * 8 + c] = t[c] * inv;
}

// ---------------- launch ----------------
extern "C" void kernel_launch(void* const* d_in, const int* in_sizes, int n_in,
                              void* d_out, int out_size) {
    const float* x       = (const float*)d_in[0];
    const int*   ei      = (const int*)d_in[1];
    const float* enc_w1  = (const float*)d_in[3];
    const float* enc_b1  = (const float*)d_in[4];
    const float* enc_w2  = (const float*)d_in[5];
    const float* enc_b2  = (const float*)d_in[6];
    const float* edge_w1 = (const float*)d_in[7];
    const float* edge_b1 = (const float*)d_in[8];
    const float* edge_w2 = (const float*)d_in[9];
    const float* edge_b2 = (const float*)d_in[10];
    const float* R_raw   = (const float*)d_in[11];
    const float* rsl     = (const float*)d_in[12];
    const float* mlogit  = (const float*)d_in[13];
    float* out = (float*)d_out;

    cudaFuncSetAttribute(k_encoder, cudaFuncAttributeMaxDynamicSharedMemorySize, 40960);

    int PB = (E2n + 255) / 256;

    k_prep_all<<<(11 * NN * 8 + 255) / 256, 256>>>(R_raw, rsl, edge_w1, enc_w1); // 0
    k_deg<<<(EE + 255) / 256, 256>>>(ei);                                        // 1
    k_encoder<<<(NN + 63) / 64, 256, 40960>>>(x, enc_b1, enc_w2, enc_b2);        // 2 (+logdeg)
    k_edgemlp<<<PB, 256>>>(ei, edge_w1, edge_b1, edge_w2, edge_b2);              // 3 <- profiled
    k_initA<<<PB, 256>>>(ei);                                                    // 4
    for (int t = 0; t < 10; t++)
        k_bp<<<PB, 256>>>(ei, mlogit, t);                                        // 5..14
    k_belief<<<(NN + 255) / 256, 256>>>(mlogit, out);                            // 15
}

// round 13
// speedup vs baseline: 1.1302x; 1.0225x over previous
#include <cuda_runtime.h>
#include <cuda_fp16.h>
#include <math.h>

#define NN   50000
#define E2n  400000
#define EE   800000

typedef unsigned long long ull;
typedef unsigned int uint;

// ---------------- scratch ----------------
__device__ __align__(16) __half g_h16[(size_t)NN * 256];     // 25.6 MB
__device__ __align__(16) float g_lp[(size_t)NN * 8];
__device__ float g_deg[NN];
__device__ float g_logdeg[NN];
__device__ float g_w[E2n];
__device__ float g_enorm[E2n];                               // rsqrt(..)*ln2
__device__ __align__(16) __half g_m16[(size_t)EE * 8];       // fp16 messages
__device__ __align__(16) __half g_logf16[2][(size_t)EE * 8];
__device__ __align__(32) float g_sumin[11][(size_t)NN * 8];  // pre-zeroed
__device__ __align__(16) float g_R[64];                      // R * log2(e)
__device__ __align__(16) __half g_Wab16[512 * 64];           // edge_w1, [p0..p7,d0..d7] chunked
__device__ __align__(16) __half g_w1h[512 * 256];
__device__ __align__(16) __half g_w1l[512 * 256];

// ---------------- helpers ----------------
__device__ __forceinline__ void red_add_v4(float* p, float a, float b, float c, float d) {
    ull gp = (ull)__cvta_generic_to_global(p);
    asm volatile("red.global.add.v4.f32 [%0], {%1,%2,%3,%4};"
                 :: "l"(gp), "f"(a), "f"(b), "f"(c), "f"(d) : "memory");
}
__device__ __forceinline__ unsigned smem_u32(const void* p) {
    unsigned a;
    asm("{ .reg .u64 t; cvta.to.shared.u64 t, %1; cvt.u32.u64 %0, t; }" : "=r"(a) : "l"(p));
    return a;
}
__device__ __forceinline__ void cpa16(uint saddr, const void* g) {
    asm volatile("cp.async.cg.shared.global [%0], [%1], 16;" :: "r"(saddr), "l"(g));
}
#define CPA_COMMIT() asm volatile("cp.async.commit_group;")
#define CPA_WAIT1()  asm volatile("cp.async.wait_group 1;")
#define CPA_WAIT0()  asm volatile("cp.async.wait_group 0;")
__device__ __forceinline__ void ldsm4(uint& a, uint& b, uint& c, uint& d, uint addr) {
    asm volatile("ldmatrix.sync.aligned.m8n8.x4.shared.b16 {%0,%1,%2,%3}, [%4];"
                 : "=r"(a), "=r"(b), "=r"(c), "=r"(d) : "r"(addr));
}
__device__ __forceinline__ void ldsm4t(uint& a, uint& b, uint& c, uint& d, uint addr) {
    asm volatile("ldmatrix.sync.aligned.m8n8.x4.trans.shared.b16 {%0,%1,%2,%3}, [%4];"
                 : "=r"(a), "=r"(b), "=r"(c), "=r"(d) : "r"(addr));
}
__device__ __forceinline__ void mma16816(float* acc, const uint* a, uint b0, uint b1) {
    asm volatile("mma.sync.aligned.m16n8k16.row.col.f32.f16.f16.f32 "
                 "{%0,%1,%2,%3}, {%4,%5,%6,%7}, {%8,%9}, {%0,%1,%2,%3};"
                 : "+f"(acc[0]), "+f"(acc[1]), "+f"(acc[2]), "+f"(acc[3])
                 : "r"(a[0]), "r"(a[1]), "r"(a[2]), "r"(a[3]), "r"(b0), "r"(b1));
}
__device__ __forceinline__ uint4 pack8h(const float* v) {
    __half2 a = __floats2half2_rn(v[0], v[1]);
    __half2 b = __floats2half2_rn(v[2], v[3]);
    __half2 c = __floats2half2_rn(v[4], v[5]);
    __half2 d = __floats2half2_rn(v[6], v[7]);
    return make_uint4(*(uint*)&a, *(uint*)&b, *(uint*)&c, *(uint*)&d);
}
__device__ __forceinline__ void unpack8h(uint4 u, float* v) {
    float2 a = __half22float2(*(__half2*)&u.x);
    float2 b = __half22float2(*(__half2*)&u.y);
    float2 c = __half22float2(*(__half2*)&u.z);
    float2 d = __half22float2(*(__half2*)&u.w);
    v[0] = a.x; v[1] = a.y; v[2] = b.x; v[3] = b.y;
    v[4] = c.x; v[5] = c.y; v[6] = d.x; v[7] = d.y;
}

// ---------------- launch 0: prep ----------------
__global__ void k_prep_all(const float* __restrict__ R_raw, const float* __restrict__ rsl,
                           const float* __restrict__ ew1, const float* __restrict__ encw1) {
    int i = blockIdx.x * 256 + threadIdx.x;
    if (i < 11 * NN * 8) ((float*)g_sumin)[i] = 0.0f;
    if (i < NN) g_deg[i] = 0.0f;
    if (i < 512 * 64) {
        // k-chunk layout: chunk ch (16 k's): q<8 -> p-weight of elem 8ch+q,
        //                                   q>=8 -> d-weight of elem 8ch+(q-8)
        int k = i >> 6, j = i & 63;
        int cc = j >> 3, u = j & 7;
        int pos = (k << 6) + (((cc ^ (k & 7)) << 3) + u);
        int ch = k >> 4, q = k & 15;
        int srcrow = (q < 8) ? (8 * ch + q) : (256 + 8 * ch + (q - 8));
        g_Wab16[pos] = __float2half_rn(ew1[srcrow * 64 + j]);
    }
    if (i < 512 * 256) {
        float v = encw1[i];
        __half h = __float2half_rn(v);
        g_w1h[i] = h;
        g_w1l[i] = __float2half_rn(v - __half2float(h));
    }
    if (i < 64) {
        int r = i >> 3, c = i & 7;
        float v = 0.5f * (R_raw[r * 8 + c] + R_raw[c * 8 + r]);
        float s = log1pf(expf(rsl[0])) + 1e-6f;
        g_R[i] = s * tanhf(v) * 1.44269504088896f;
    }
}

// ---------------- launch 1: degree ----------------
__global__ void k_deg(const int* __restrict__ ei) {
    int e = blockIdx.x * blockDim.x + threadIdx.x;
    if (e < EE) atomicAdd(&g_deg[ei[e]], 1.0f);
}

// ---------------- launch 2: encoder (unchanged from R11) ----------------
extern __shared__ char enc_pool[];
__global__ void __launch_bounds__(256, 2) k_encoder(const float* __restrict__ x,
                                                    const float* __restrict__ b1,
                                                    const float* __restrict__ w2,
                                                    const float* __restrict__ b2) {
    __shared__ float w2s[256][8];
    __shared__ float b1s[256];
    __shared__ float slog[64][8];
    char* pool = enc_pool;
    uint pbase = smem_u32(pool);
    int tid = threadIdx.x, lane = tid & 31, wid = tid >> 5;
    int mw = wid & 3, nw = wid >> 2;

    if (blockIdx.x < (NN + 255) / 256) {
        int n = blockIdx.x * 256 + tid;
        if (n < NN) g_logdeg[n] = __logf(g_deg[n] + 1.0f);
    }
    for (int i = tid; i < 2048; i += 256) w2s[i >> 3][i & 7] = w2[i];
    if (tid < 256) b1s[tid] = b1[tid];
    for (int i = tid; i < 512; i += 256) ((float*)slog)[i] = 0.0f;

    int n0 = blockIdx.x * 64;

    auto stageA = [&](int kt, int buf) {
        if (tid < 128) {
            int r = tid >> 1, c = tid & 1;
            int gn = min(n0 + r, NN - 1);
            const float4* xr = (const float4*)x + (size_t)gn * 128 + kt * 4 + c * 2;
            float4 f0 = xr[0], f1 = xr[1];
            float v[8] = {f0.x, f0.y, f0.z, f0.w, f1.x, f1.y, f1.z, f1.w};
            __half hi[8], lo[8];
#pragma unroll
            for (int q = 0; q < 8; q++) {
                __half h = __float2half_rn(v[q]);
                hi[q] = h;
                lo[q] = __float2half_rn(v[q] - __half2float(h));
            }
            int cp = c ^ ((r >> 2) & 1);
            *(uint4*)(pool + (buf * 2 + 0) * 2048 + r * 32 + cp * 16) = *(uint4*)hi;
            *(uint4*)(pool + (buf * 2 + 1) * 2048 + r * 32 + cp * 16) = *(uint4*)lo;
        }
    };
    auto stageB = [&](int kt, int buf) {
#pragma unroll
        for (int q = 0; q < 4; q++) {
            int id = tid + 256 * q;
            int which = id >> 9, rem = id & 511, k = rem >> 5, cu = rem & 31;
            const char* src = (const char*)(which ? g_w1l : g_w1h)
                              + (((size_t)(kt * 16 + k) * 32 + cu) << 4);
            int cp = cu ^ (k & 7);
            cpa16(pbase + 8192 + (buf * 2 + which) * 8192 + k * 512 + cp * 16, src);
        }
    };

    stageA(0, 0); stageB(0, 0); CPA_COMMIT();

    float acc[16][4];
#pragma unroll
    for (int t = 0; t < 16; t++)
#pragma unroll
        for (int q = 0; q < 4; q++) acc[t][q] = 0.0f;

    int q4 = lane >> 3, l8 = lane & 7;
    int arow = mw * 16 + (q4 & 1) * 8 + l8;
    uint aoff = (uint)(arow * 32 + (((q4 >> 1) ^ ((arow >> 2) & 1)) * 16));
    int bk = lane & 15, chi = lane >> 4;
    uint bko = (uint)(bk * 512);

    for (int kt = 0; kt < 32; kt++) {
        int buf = kt & 1;
        if (kt < 31) {
            stageA(kt + 1, buf ^ 1); stageB(kt + 1, buf ^ 1); CPA_COMMIT();
            CPA_WAIT1();
        } else {
            CPA_WAIT0();
        }
        __syncthreads();
        uint a1b = pbase + (buf * 2 + 0) * 2048 + aoff;
        uint a2b = pbase + (buf * 2 + 1) * 2048 + aoff;
        uint bhb = pbase + 8192 + (buf * 2 + 0) * 8192 + bko;
        uint blb = pbase + 8192 + (buf * 2 + 1) * 8192 + bko;
        uint A1[4], A2[4];
        ldsm4(A1[0], A1[1], A1[2], A1[3], a1b);
        ldsm4(A2[0], A2[1], A2[2], A2[3], a2b);
#pragma unroll
        for (int t = 0; t < 8; t++) {
            int chunk = nw * 16 + t * 2 + chi;
            uint coff = (uint)((chunk ^ (bk & 7)) * 16);
            uint h0, h1, h2, h3, l0, l1, l2, l3;
            ldsm4t(h0, h1, h2, h3, bhb + coff);
            ldsm4t(l0, l1, l2, l3, blb + coff);
            mma16816(acc[2 * t],     A1, h0, h1);
            mma16816(acc[2 * t + 1], A1, h2, h3);
            mma16816(acc[2 * t],     A1, l0, l1);
            mma16816(acc[2 * t + 1], A1, l2, l3);
            mma16816(acc[2 * t],     A2, h0, h1);
            mma16816(acc[2 * t + 1], A2, h2, h3);
        }
        __syncthreads();
    }

    int r = lane >> 2, c = lane & 3;
    int row0 = mw * 16 + r;
    float pl0[8], pl1[8];
#pragma unroll
    for (int k = 0; k < 8; k++) { pl0[k] = 0.0f; pl1[k] = 0.0f; }
    __half* h16s = (__half*)pool;
#pragma unroll
    for (int tt = 0; tt < 16; tt++) {
        int j0 = nw * 128 + tt * 8 + 2 * c;
        float hv0 = fmaxf(acc[tt][0] + b1s[j0],     0.0f);
        float hv1 = fmaxf(acc[tt][1] + b1s[j0 + 1], 0.0f);
        float hv2 = fmaxf(acc[tt][2] + b1s[j0],     0.0f);
        float hv3 = fmaxf(acc[tt][3] + b1s[j0 + 1], 0.0f);
        *(__half2*)(h16s + row0 * 264 + j0)       = __floats2half2_rn(hv0, hv1);
        *(__half2*)(h16s + (row0 + 8) * 264 + j0) = __floats2half2_rn(hv2, hv3);
        const float4* w2a = (const float4*)w2s[j0];
        const float4* w2b = (const float4*)w2s[j0 + 1];
        float4 a0 = w2a[0], a1 = w2a[1], b0 = w2b[0], b1v = w2b[1];
        pl0[0] += hv0 * a0.x + hv1 * b0.x;  pl0[1] += hv0 * a0.y + hv1 * b0.y;
        pl0[2] += hv0 * a0.z + hv1 * b0.z;  pl0[3] += hv0 * a0.w + hv1 * b0.w;
        pl0[4] += hv0 * a1.x + hv1 * b1v.x; pl0[5] += hv0 * a1.y + hv1 * b1v.y;
        pl0[6] += hv0 * a1.z + hv1 * b1v.z; pl0[7] += hv0 * a1.w + hv1 * b1v.w;
        pl1[0] += hv2 * a0.x + hv3 * b0.x;  pl1[1] += hv2 * a0.y + hv3 * b0.y;
        pl1[2] += hv2 * a0.z + hv3 * b0.z;  pl1[3] += hv2 * a0.w + hv3 * b0.w;
        pl1[4] += hv2 * a1.x + hv3 * b1v.x; pl1[5] += hv2 * a1.y + hv3 * b1v.y;
        pl1[6] += hv2 * a1.z + hv3 * b1v.z; pl1[7] += hv2 * a1.w + hv3 * b1v.w;
    }
#pragma unroll
    for (int k = 0; k < 8; k++) {
        pl0[k] += __shfl_xor_sync(0xffffffffu, pl0[k], 1);
        pl0[k] += __shfl_xor_sync(0xffffffffu, pl0[k], 2);
        pl1[k] += __shfl_xor_sync(0xffffffffu, pl1[k], 1);
        pl1[k] += __shfl_xor_sync(0xffffffffu, pl1[k], 2);
    }
    if (c == 0) {
#pragma unroll
        for (int k = 0; k < 8; k++) {
            atomicAdd(&slog[row0][k], pl0[k]);
            atomicAdd(&slog[row0 + 8][k], pl1[k]);
        }
    }
    __syncthreads();
#pragma unroll
    for (int i = 0; i < 8; i++) {
        int id = tid + 256 * i;
        int row = id >> 5, cu = id & 31;
        int node = n0 + row;
        if (node < NN) {
            uint4 v = ((uint4*)pool)[row * 33 + cu];
            ((uint4*)g_h16)[(size_t)node * 32 + cu] = v;
        }
    }
    if (tid < 64) {
        int node = n0 + tid;
        if (node < NN) {
            float lg[8], mx = -1e30f;
#pragma unroll
            for (int k = 0; k < 8; k++) { lg[k] = slog[tid][k] + b2[k]; mx = fmaxf(mx, lg[k]); }
            float s = 0.0f;
#pragma unroll
            for (int k = 0; k < 8; k++) s += __expf(lg[k] - mx);
            float lse = mx + __logf(s);
#pragma unroll
            for (int k = 0; k < 8; k++) g_lp[(size_t)node * 8 + k] = lg[k] - lse;
        }
    }
}

// ---------------- launch 3 (profiled): edge MLP + fused initA ----------------
__global__ void __launch_bounds__(256, 2) k_edgemlp(const int* __restrict__ ei,
                                                    const float* __restrict__ w1full,
                                                    const float* __restrict__ b1,
                                                    const float* __restrict__ w2,
                                                    const float* __restrict__ b2) {
    __shared__ uint4  stg[2][512];
    __shared__ uint4  wst[2][128];
    __shared__ float4 epi[64];
    __shared__ float  s1s[256], s2s[256];
    __shared__ float  wsh[256];
    __shared__ float  Rs[64];

    int tid  = threadIdx.x;
    int wid  = tid >> 5;
    int lane = tid & 31;
    int e0   = blockIdx.x * 256;

    uint stgb = smem_u32(stg);
    uint wstb = smem_u32(wst);

    int nsrc = ei[e0 + tid];
    int ndst = ei[EE + e0 + tid];
    const char* pA = (const char*)(g_h16 + (size_t)nsrc * 256);
    const char* pB = (const char*)(g_h16 + (size_t)ndst * 256);
    {
        float a = g_logdeg[nsrc], b = g_logdeg[ndst];
        s1s[tid] = a + b; s2s[tid] = fabsf(a - b);
    }
    if (tid < 64) {
        epi[tid] = make_float4(w1full[512 * 64 + tid], w1full[513 * 64 + tid],
                               b1[tid], w2[tid]);
        Rs[tid] = g_R[tid];
    }
    cpa16(stgb + tid * 16,        pA);
    cpa16(stgb + 4096 + tid * 16, pB);
    if (tid < 128) cpa16(wstb + tid * 16, (const char*)g_Wab16 + tid * 16);
    CPA_COMMIT();

    float acc[2][8][4];
#pragma unroll
    for (int mt = 0; mt < 2; mt++)
#pragma unroll
        for (int t = 0; t < 8; t++)
#pragma unroll
            for (int q = 0; q < 4; q++) acc[mt][t][q] = 0.0f;

    int klane = lane & 15;
    int chi   = lane >> 4;
    int xorv  = lane & 7;
    int r = lane >> 2, c = lane & 3;
    int eb = wid * 32;

    for (int kt = 0; kt < 32; kt++) {
        int buf = kt & 1;
        if (kt < 31) {
            uint db = stgb + (buf ^ 1) * 8192;
            cpa16(db + tid * 16,        pA + (kt + 1) * 16);
            cpa16(db + 4096 + tid * 16, pB + (kt + 1) * 16);
            if (tid < 128)
                cpa16(wstb + (buf ^ 1) * 2048 + tid * 16,
                      (const char*)g_Wab16 + (kt + 1) * 2048 + tid * 16);
            CPA_COMMIT();
            CPA_WAIT1();
        } else {
            CPA_WAIT0();
        }
        __syncthreads();
        const __half* hb = (const __half*)stg + buf * 4096;
        unsigned wbase = wstb + buf * 2048 + (unsigned)(klane * 128);

        // A-fragments via half2: chunk k-layout [p0..p7, d0..d7]
        unsigned afr[2][4];
#pragma unroll
        for (int mt = 0; mt < 2; mt++) {
            int e1 = eb + mt * 16 + r;
            int e2 = e1 + 8;
            __half2 hs1 = *(const __half2*)&hb[e1 * 8 + 2 * c];
            __half2 hd1 = *(const __half2*)&hb[2048 + e1 * 8 + 2 * c];
            __half2 hs2 = *(const __half2*)&hb[e2 * 8 + 2 * c];
            __half2 hd2 = *(const __half2*)&hb[2048 + e2 * 8 + 2 * c];
            __half2 P1 = __hmul2(hs1, hd1);
            __half2 P2 = __hmul2(hs2, hd2);
            __half2 D1 = __habs2(__hsub2(hs1, hd1));
            __half2 D2 = __habs2(__hsub2(hs2, hd2));
            afr[mt][0] = *(unsigned*)&P1; afr[mt][1] = *(unsigned*)&P2;
            afr[mt][2] = *(unsigned*)&D1; afr[mt][3] = *(unsigned*)&D2;
        }
#pragma unroll
        for (int t = 0; t < 4; t++) {
            unsigned b0, b1r, b2r, b3;
            unsigned addr = wbase + (unsigned)((((2 * t + chi) ^ xorv) << 4));
            ldsm4t(b0, b1r, b2r, b3, addr);
#pragma unroll
            for (int mt = 0; mt < 2; mt++) {
                mma16816(acc[mt][2 * t],     afr[mt], b0,  b1r);
                mma16816(acc[mt][2 * t + 1], afr[mt], b2r, b3);
            }
        }
        __syncthreads();
    }

    float b2v = b2[0];
#pragma unroll
    for (int mt = 0; mt < 2; mt++) {
        int er  = eb + mt * 16 + r;
        int er8 = er + 8;
        float s1r = s1s[er], s2r = s2s[er];
        float s18 = s1s[er8], s28 = s2s[er8];
        float vr = 0.0f, v8 = 0.0f;
#pragma unroll
        for (int t = 0; t < 8; t++) {
#pragma unroll
            for (int u = 0; u < 2; u++) {
                float4 pp = epi[t * 8 + c * 2 + u];
                float pre  = acc[mt][t][u]     + s1r * pp.x + s2r * pp.y + pp.z;
                float pre8 = acc[mt][t][2 + u] + s18 * pp.x + s28 * pp.y + pp.z;
                vr += fmaxf(pre, 0.0f) * pp.w;
                v8 += fmaxf(pre8, 0.0f) * pp.w;
            }
        }
        vr += __shfl_xor_sync(0xffffffffu, vr, 1);
        vr += __shfl_xor_sync(0xffffffffu, vr, 2);
        v8 += __shfl_xor_sync(0xffffffffu, v8, 1);
        v8 += __shfl_xor_sync(0xffffffffu, v8, 2);
        if (c == 0) {
            wsh[er]  = 0.8f / (1.0f + __expf(-(vr + b2v)));
            wsh[er8] = 0.8f / (1.0f + __expf(-(v8 + b2v)));
        }
    }
    __syncthreads();

    // ---- fused initA: pair p = e0 + tid ----
    int p = e0 + tid;
    if (p < E2n) {
        float w = wsh[tid];
        int s = nsrc, d = ndst;
        g_w[p] = w;
        float en = rsqrtf(fmaxf(g_deg[s], 1.0f) * fmaxf(g_deg[d], 1.0f)) * 0.6931471805599453f;
        g_enorm[p] = en;
        const float4* ls4 = (const float4*)(g_lp + (size_t)s * 8);
        const float4* ld4 = (const float4*)(g_lp + (size_t)d * 8);
        float4 sA = ls4[0], sB = ls4[1], dA = ld4[0], dB = ld4[1];
        float mf[8] = {sA.x, sA.y, sA.z, sA.w, sB.x, sB.y, sB.z, sB.w};
        float mb[8] = {dA.x, dA.y, dA.z, dA.w, dB.x, dB.y, dB.z, dB.w};
        float sf = 0.0f, sb = 0.0f;
#pragma unroll
        for (int cc = 0; cc < 8; cc++) { mf[cc] = __expf(mf[cc]); sf += mf[cc];
                                         mb[cc] = __expf(mb[cc]); sb += mb[cc]; }
        float isf = 1.0f / sf, isb = 1.0f / sb;
#pragma unroll
        for (int cc = 0; cc < 8; cc++) { mf[cc] *= isf; mb[cc] *= isb; }
        ((uint4*)g_m16)[p]       = pack8h(mf);
        ((uint4*)g_m16)[p + E2n] = pack8h(mb);
        float ff[8] = {0,0,0,0,0,0,0,0}, fb[8] = {0,0,0,0,0,0,0,0};
#pragma unroll
        for (int cc = 0; cc < 8; cc++)
#pragma unroll
            for (int dd = 0; dd < 8; dd++) {
                float kv = exp2f(w * Rs[cc * 8 + dd]);
                ff[dd] += mf[cc] * kv;
                fb[dd] += mb[cc] * kv;
            }
        float lff[8], lfb[8];
#pragma unroll
        for (int i = 0; i < 8; i++) {
            lff[i] = __log2f(fmaxf(ff[i], 1e-12f)) * en;
            lfb[i] = __log2f(fmaxf(fb[i], 1e-12f)) * en;
        }
        ((uint4*)g_logf16[0])[p]       = pack8h(lff);
        ((uint4*)g_logf16[0])[p + E2n] = pack8h(lfb);
        float* spd = &g_sumin[0][(size_t)d * 8];
        float* sps = &g_sumin[0][(size_t)s * 8];
        red_add_v4(spd,     lff[0], lff[1], lff[2], lff[3]);
        red_add_v4(spd + 4, lff[4], lff[5], lff[6], lff[7]);
        red_add_v4(sps,     lfb[0], lfb[1], lfb[2], lfb[3]);
        red_add_v4(sps + 4, lfb[4], lfb[5], lfb[6], lfb[7]);
    }
}

// ---------------- BP step t (pairs): B(t) then A(t+1) ----------------
__global__ void __launch_bounds__(256) k_bp(const int* __restrict__ ei,
                                            const float* __restrict__ mlogit, int t) {
    __shared__ float Rs[64];
    if (threadIdx.x < 64) Rs[threadIdx.x] = g_R[threadIdx.x];
    __syncthreads();
    int p = blockIdx.x * 256 + threadIdx.x;
    if (p >= E2n) return;
    int pr = t & 1;
    float alpha = 1.5f / (1.0f + __expf(-mlogit[0]));
    int s = ei[p], d = ei[EE + p];
    float w = g_w[p], en = g_enorm[p];
    const float4* sis4 = (const float4*)(g_sumin[t] + (size_t)s * 8);
    const float4* sid4 = (const float4*)(g_sumin[t] + (size_t)d * 8);
    const float4* ls4  = (const float4*)(g_lp + (size_t)s * 8);
    const float4* ld4  = (const float4*)(g_lp + (size_t)d * 8);
    uint4 vlf = ((const uint4*)g_logf16[pr])[p];
    uint4 vlb = ((const uint4*)g_logf16[pr])[p + E2n];
    uint4 vmf = ((const uint4*)g_m16)[p];
    uint4 vmb = ((const uint4*)g_m16)[p + E2n];

    float4 sisA = sis4[0], sisB = sis4[1], sidA = sid4[0], sidB = sid4[1];
    float4 lsA = ls4[0], lsB = ls4[1], ldA = ld4[0], ldB = ld4[1];
    float sis[8] = {sisA.x, sisA.y, sisA.z, sisA.w, sisB.x, sisB.y, sisB.z, sisB.w};
    float sid[8] = {sidA.x, sidA.y, sidA.z, sidA.w, sidB.x, sidB.y, sidB.z, sidB.w};
    float lps[8] = {lsA.x, lsA.y, lsA.z, lsA.w, lsB.x, lsB.y, lsB.z, lsB.w};
    float lpd[8] = {ldA.x, ldA.y, ldA.z, ldA.w, ldB.x, ldB.y, ldB.z, ldB.w};
    float lfp[8], lbp[8];
    unpack8h(vlf, lfp);
    unpack8h(vlb, lbp);

    float tf[8], tb[8], mxf = -1e30f, mxb = -1e30f;
#pragma unroll
    for (int i = 0; i < 8; i++) {
        tf[i] = lps[i] + alpha * (sis[i] - lbp[i]);
        tb[i] = lpd[i] + alpha * (sid[i] - lfp[i]);
        mxf = fmaxf(mxf, tf[i]); mxb = fmaxf(mxb, tb[i]);
    }
    float ssf = 0.0f, ssb = 0.0f;
#pragma unroll
    for (int i = 0; i < 8; i++) {
        tf[i] = __expf(tf[i] - mxf); ssf += tf[i];
        tb[i] = __expf(tb[i] - mxb); ssb += tb[i];
    }
    float ivf = 0.2f / ssf, ivb = 0.2f / ssb;
    float mf[8], mb[8];
    unpack8h(vmf, mf);
    unpack8h(vmb, mb);
    float s2f = 0.0f, s2b = 0.0f;
#pragma unroll
    for (int i = 0; i < 8; i++) {
        mf[i] = fmaxf(0.8f * mf[i] + tf[i] * ivf, 1e-12f); s2f += mf[i];
        mb[i] = fmaxf(0.8f * mb[i] + tb[i] * ivb, 1e-12f); s2b += mb[i];
    }
    float i2f = 1.0f / s2f, i2b = 1.0f / s2b;
#pragma unroll
    for (int i = 0; i < 8; i++) { mf[i] *= i2f; mb[i] *= i2b; }
    ((uint4*)g_m16)[p]       = pack8h(mf);
    ((uint4*)g_m16)[p + E2n] = pack8h(mb);

    float ff[8] = {0,0,0,0,0,0,0,0}, fb[8] = {0,0,0,0,0,0,0,0};
#pragma unroll
    for (int c = 0; c < 8; c++)
#pragma unroll
        for (int dd = 0; dd < 8; dd++) {
            float kv = exp2f(w * Rs[c * 8 + dd]);
            ff[dd] += mf[c] * kv;
            fb[dd] += mb[c] * kv;
        }
    float lff[8], lfb[8];
#pragma unroll
    for (int i = 0; i < 8; i++) {
        lff[i] = __log2f(fmaxf(ff[i], 1e-12f)) * en;
        lfb[i] = __log2f(fmaxf(fb[i], 1e-12f)) * en;
    }
    ((uint4*)g_logf16[pr ^ 1])[p]       = pack8h(lff);
    ((uint4*)g_logf16[pr ^ 1])[p + E2n] = pack8h(lfb);
    float* spd = &g_sumin[t + 1][(size_t)d * 8];
    float* sps = &g_sumin[t + 1][(size_t)s * 8];
    red_add_v4(spd,     lff[0], lff[1], lff[2], lff[3]);
    red_add_v4(spd + 4, lff[4], lff[5], lff[6], lff[7]);
    red_add_v4(sps,     lfb[0], lfb[1], lfb[2], lfb[3]);
    red_add_v4(sps + 4, lfb[4], lfb[5], lfb[6], lfb[7]);
}

// ---------------- final beliefs ----------------
__global__ void k_belief(const float* __restrict__ mlogit, float* __restrict__ out) {
    int n = blockIdx.x * blockDim.x + threadIdx.x;
    if (n >= NN) return;
    float alpha = 1.5f / (1.0f + __expf(-mlogit[0]));
    float t[8], mx = -1e30f;
#pragma unroll
    for (int c = 0; c < 8; c++) {
        t[c] = g_lp[(size_t)n * 8 + c] + alpha * g_sumin[10][(size_t)n * 8 + c];
        mx = fmaxf(mx, t[c]);
    }
    float sum = 0.0f;
#pragma unroll
    for (int c = 0; c < 8; c++) { t[c] = __expf(t[c] - mx); sum += t[c]; }
    float inv = 1.0f / sum;
#pragma unroll
    for (int c = 0; c < 8; c++) out[(size_t)n * 8 + c] = t[c] * inv;
}

// ---------------- launch ----------------
extern "C" void kernel_launch(void* const* d_in, const int* in_sizes, int n_in,
                              void* d_out, int out_size) {
    const float* x       = (const float*)d_in[0];
    const int*   ei      = (const int*)d_in[1];
    const float* enc_w1  = (const float*)d_in[3];
    const float* enc_b1  = (const float*)d_in[4];
    const float* enc_w2  = (const float*)d_in[5];
    const float* enc_b2  = (const float*)d_in[6];
    const float* edge_w1 = (const float*)d_in[7];
    const float* edge_b1 = (const float*)d_in[8];
    const float* edge_w2 = (const float*)d_in[9];
    const float* edge_b2 = (const float*)d_in[10];
    const float* R_raw   = (const float*)d_in[11];
    const float* rsl     = (const float*)d_in[12];
    const float* mlogit  = (const float*)d_in[13];
    float* out = (float*)d_out;

    cudaFuncSetAttribute(k_encoder, cudaFuncAttributeMaxDynamicSharedMemorySize, 40960);

    int PB = (E2n + 255) / 256;

    k_prep_all<<<(11 * NN * 8 + 255) / 256, 256>>>(R_raw, rsl, edge_w1, enc_w1); // 0
    k_deg<<<(EE + 255) / 256, 256>>>(ei);                                        // 1
    k_encoder<<<(NN + 63) / 64, 256, 40960>>>(x, enc_b1, enc_w2, enc_b2);        // 2 (+logdeg)
    k_edgemlp<<<PB, 256>>>(ei, edge_w1, edge_b1, edge_w2, edge_b2);              // 3 <- profiled (+initA)
    for (int t = 0; t < 10; t++)
        k_bp<<<PB, 256>>>(ei, mlogit, t);                                        // 4..13
    k_belief<<<(NN + 255) / 256, 256>>>(mlogit, out);                            // 14
}